// round 16
// baseline (speedup 1.0000x reference)
#include <cuda_runtime.h>
#include <math_constants.h>
#include <cstdint>

#define C        32000
#define C4       (C / 4)            // 8000 float4 per row
#define C8       (C / 8)            // 4000 float8 per row
#define GRID_PTS 100
#define NMIDS    (GRID_PTS - 1)
#define THREADS  1024
#define NWARP    32
#define CHUNKS8  4                  // ceil(C8 / THREADS)

// first read of a row: 256-bit LDG, pinned in L2 until its binning re-read.
// sm_103a ptxas only allows L2::evict_last on .v8.b32 / .v4.b64.
__device__ __forceinline__ void ldg8_evict_last(const float* p, float4& a, float4& b) {
    uint32_t x0, x1, x2, x3, x4, x5, x6, x7;
    asm("ld.global.L2::evict_last.v8.b32 {%0,%1,%2,%3,%4,%5,%6,%7}, [%8];"
        : "=r"(x0), "=r"(x1), "=r"(x2), "=r"(x3),
          "=r"(x4), "=r"(x5), "=r"(x6), "=r"(x7)
        : "l"(p));
    a.x = __uint_as_float(x0); a.y = __uint_as_float(x1);
    a.z = __uint_as_float(x2); a.w = __uint_as_float(x3);
    b.x = __uint_as_float(x4); b.y = __uint_as_float(x5);
    b.z = __uint_as_float(x6); b.w = __uint_as_float(x7);
}

__global__ __launch_bounds__(THREADS, 2)
void calib_kernel(const float* __restrict__ logits,
                  const float* __restrict__ log_temp,
                  const float* __restrict__ iso_x,
                  const float* __restrict__ iso_y,
                  float* __restrict__ out,
                  int rows, int nblk)
{
    __shared__ float log2m[NMIDS];      // fixed: log2(midpoint[i])
    __shared__ float ybuf[GRID_PTS];
    __shared__ float redm[2][NWARP];    // per-warp (m,s) deposits, by row parity
    __shared__ float reds[2][NWARP];
    __shared__ float cbox[2];           // per-row scalar c = M + log2(S), by parity

    const int tid  = threadIdx.x;
    const int lane = tid & 31;
    const int wid  = tid >> 5;

    int rk = blockIdx.x;
    if (rk >= rows) return;

    // temperature = clamp(exp(log_T), 0.1, 10); fold log2(e)/T into the scale
    const float T  = fminf(fmaxf(expf(log_temp[0]), 0.1f), 10.0f);
    const float s2 = 1.4426950408889634f / T;   // base-2 scale

    if (tid < GRID_PTS) ybuf[tid] = iso_y[tid];
    // thr_i = log2(mids_i * S) + M = log2m[i] + c  ->  count(log2m[i] < x*s2 - c)
    if (tid < NMIDS) log2m[tid] = log2f(0.5f * (iso_x[tid] + iso_x[tid + 1]));

    // per-float4 fused online-softmax accumulate
    auto acc4 = [&s2](float4 v, float& m, float& s) {
        v.x *= s2; v.y *= s2; v.z *= s2; v.w *= s2;
        float mx = fmaxf(fmaxf(v.x, v.y), fmaxf(v.z, v.w));
        if (mx > m) { s *= exp2f(m - mx); m = mx; }           // rare rescale
        s += (exp2f(v.x - m) + exp2f(v.y - m)) + (exp2f(v.z - m) + exp2f(v.w - m));
    };

    // stream-read row r (DRAM, evict_last) with fused online (m,s); deposit at parity p
    auto stream_read_deposit = [&](int r, int p) {
        const float* src = logits + (long long)r * C;
        float m = -CUDART_INF_F, s = 0.0f;
        #pragma unroll
        for (int k = 0; k < CHUNKS8; k++) {
            const int idx = tid + k * THREADS;
            if (idx < C8) {
                float4 a, b;
                ldg8_evict_last(src + (size_t)idx * 8, a, b);
                acc4(a, m, s);
                acc4(b, m, s);
            }
        }
        #pragma unroll
        for (int o = 16; o; o >>= 1) {
            float mo = __shfl_xor_sync(0xffffffffu, m, o);
            float so = __shfl_xor_sync(0xffffffffu, s, o);
            float nm = fmaxf(m, mo);
            s = s * exp2f(m - nm) + so * exp2f(mo - nm);
            m = nm;
        }
        if (lane == 0) { redm[p][wid] = m; reds[p][wid] = s; }
    };

    // warp 0 only: combine 32 per-warp deposits at parity p -> scalar c
    auto finalize = [&](int p) {
        float mm = redm[p][lane];
        float ss = reds[p][lane];
        #pragma unroll
        for (int o = 16; o; o >>= 1) {
            float mo = __shfl_xor_sync(0xffffffffu, mm, o);
            float so = __shfl_xor_sync(0xffffffffu, ss, o);
            float nm = fmaxf(mm, mo);
            ss = ss * exp2f(mm - nm) + so * exp2f(mo - nm);
            mm = nm;
        }
        if (lane == 0) cbox[p] = mm + log2f(ss);
    };

    // bin one float4 of raw logits against (log2m, c), producing y values
    auto bin4 = [&](float4 v, float c, float l0, float y0) {
        float4 r;
        float* vp = &v.x;
        float* rp = &r.x;
        #pragma unroll
        for (int j = 0; j < 4; j++) {
            const float w = fmaf(vp[j], s2, -c);
            if (w <= l0) {
                rp[j] = y0;               // warp-uniform fast path (~all of a softmax row)
            } else {
                int lo = 1, hi = NMIDS;   // log2m[0] < w already established
                while (lo < hi) {
                    int mid = (lo + hi) >> 1;
                    if (log2m[mid] < w) lo = mid + 1; else hi = mid;
                }
                rp[j] = ybuf[lo];
            }
        }
        return r;
    };

    // ---- prologue: fill the 2-deep pipeline ----
    stream_read_deposit(rk, 0);                 // row_0 (also publishes log2m/ybuf at next barrier)
    __syncthreads();
    int rk1 = rk + nblk;
    if (wid == 0) finalize(0);                  // c for row_0
    if (rk1 < rows) stream_read_deposit(rk1, 1);
    __syncthreads();

    // ---- steady state: finalize row k+1 (warp0) ∥ read row k+2 ∥ bin+write row k ----
    int parity = 0;
    for (;;) {
        const int  rk2 = rk1 + nblk;
        const bool h1  = rk1 < rows;
        const bool h2  = rk2 < rows;

        if (wid == 0 && h1) finalize(parity ^ 1);   // hidden under streaming below

        const float c  = cbox[parity];
        const float l0 = log2m[0];
        const float y0 = ybuf[0];
        const float*  np = logits + (long long)rk2 * C;
        const float4* cp = reinterpret_cast<const float4*>(logits + (long long)rk * C);
        float4*       op = reinterpret_cast<float4*>(out + (long long)rk * C);

        float m = -CUDART_INF_F, s = 0.0f;
        #pragma unroll
        for (int k = 0; k < CHUNKS8; k++) {
            const int idx = tid + k * THREADS;       // float8 units
            const bool ok = idx < C8;
            if (h2 & ok) {                           // DRAM read of row k+2 (pinned in L2)
                float4 a, b;
                ldg8_evict_last(np + (size_t)idx * 8, a, b);
                acc4(a, m, s);
                acc4(b, m, s);
            }
            if (ok) {                                // L2 re-read (streaming), bin, DRAM write
                const int i4 = idx * 2;
                float4 v0 = __ldcs(cp + i4);
                float4 v1 = __ldcs(cp + i4 + 1);
                __stcs(op + i4,     bin4(v0, c, l0, y0));
                __stcs(op + i4 + 1, bin4(v1, c, l0, y0));
            }
        }

        if (h2) {                                    // deposit (m,s) for row_{k+2}
            #pragma unroll
            for (int o = 16; o; o >>= 1) {
                float mo = __shfl_xor_sync(0xffffffffu, m, o);
                float so = __shfl_xor_sync(0xffffffffu, s, o);
                float nm = fmaxf(m, mo);
                s = s * exp2f(m - nm) + so * exp2f(mo - nm);
                m = nm;
            }
            if (lane == 0) { redm[parity][wid] = m; reds[parity][wid] = s; }
        }

        if (!h1) break;
        __syncthreads();                             // one barrier per row
        rk = rk1; rk1 = rk2; parity ^= 1;
    }
}

extern "C" void kernel_launch(void* const* d_in, const int* in_sizes, int n_in,
                              void* d_out, int out_size) {
    const float* logits   = (const float*)d_in[0];
    const float* log_temp = (const float*)d_in[1];
    const float* iso_x    = (const float*)d_in[2];
    const float* iso_y    = (const float*)d_in[3];
    float* out = (float*)d_out;

    const int rows = out_size / C;
    int nblk = 2 * 148;                 // 2 persistent CTAs per SM
    if (nblk > rows) nblk = rows;

    calib_kernel<<<nblk, THREADS>>>(logits, log_temp, iso_x, iso_y, out, rows, nblk);
}

// round 17
// speedup vs baseline: 1.4111x; 1.4111x over previous
#include <cuda_runtime.h>
#include <math_constants.h>
#include <cstdint>

#define C        32000
#define C4       (C / 4)            // 8000 float4 per row
#define C8       (C / 8)            // 4000 float8 per row
#define GRID_PTS 100
#define NMIDS    (GRID_PTS - 1)
#define THREADS  1024
#define NWARP    32
#define CHUNKS8  4                  // ceil(C8 / THREADS)

// phase-1 read: 256-bit LDG pinned in L2 until this CTA's phase-2 re-read (~2us).
// sm_103a ptxas only allows L2::evict_last on .v8.b32 / .v4.b64.
__device__ __forceinline__ void ldg8_evict_last(const float* p, float4& a, float4& b) {
    uint32_t x0, x1, x2, x3, x4, x5, x6, x7;
    asm("ld.global.L2::evict_last.v8.b32 {%0,%1,%2,%3,%4,%5,%6,%7}, [%8];"
        : "=r"(x0), "=r"(x1), "=r"(x2), "=r"(x3),
          "=r"(x4), "=r"(x5), "=r"(x6), "=r"(x7)
        : "l"(p));
    a.x = __uint_as_float(x0); a.y = __uint_as_float(x1);
    a.z = __uint_as_float(x2); a.w = __uint_as_float(x3);
    b.x = __uint_as_float(x4); b.y = __uint_as_float(x5);
    b.z = __uint_as_float(x6); b.w = __uint_as_float(x7);
}

__global__ __launch_bounds__(THREADS, 2)
void calib_kernel(const float* __restrict__ logits,
                  const float* __restrict__ log_temp,
                  const float* __restrict__ iso_x,
                  const float* __restrict__ iso_y,
                  float* __restrict__ out)
{
    __shared__ float log2m[NMIDS];      // fixed: log2(midpoint[i])
    __shared__ float ybuf[GRID_PTS];
    __shared__ float redm[NWARP];
    __shared__ float reds[NWARP];
    __shared__ float cbox;              // per-row scalar c = M + log2(S)

    const int tid  = threadIdx.x;
    const int lane = tid & 31;
    const int wid  = tid >> 5;
    const long long row = blockIdx.x;

    // temperature = clamp(exp(log_T), 0.1, 10); fold log2(e)/T into the scale
    const float T  = fminf(fmaxf(expf(log_temp[0]), 0.1f), 10.0f);
    const float s2 = 1.4426950408889634f / T;   // base-2 scale

    if (tid < GRID_PTS) ybuf[tid] = iso_y[tid];
    // thr_i = log2(mids_i * S) + M = log2m[i] + c  ->  count(log2m[i] < x*s2 - c)
    if (tid < NMIDS) log2m[tid] = log2f(0.5f * (iso_x[tid] + iso_x[tid + 1]));

    const float* rowp = logits + row * (long long)C;

    // ---- Phase 1: single DRAM read (256-bit, pinned) + fused online (m,s) ----
    float m = -CUDART_INF_F;
    float s = 0.0f;
    #pragma unroll
    for (int k = 0; k < CHUNKS8; k++) {
        const int idx = tid + k * THREADS;
        if (idx < C8) {
            float4 a, b;
            ldg8_evict_last(rowp + (size_t)idx * 8, a, b);
            a.x *= s2; a.y *= s2; a.z *= s2; a.w *= s2;
            b.x *= s2; b.y *= s2; b.z *= s2; b.w *= s2;
            float mx = fmaxf(fmaxf(fmaxf(a.x, a.y), fmaxf(a.z, a.w)),
                             fmaxf(fmaxf(b.x, b.y), fmaxf(b.z, b.w)));
            if (mx > m) { s *= exp2f(m - mx); m = mx; }   // rare rescale
            s += ((exp2f(a.x - m) + exp2f(a.y - m)) + (exp2f(a.z - m) + exp2f(a.w - m)))
               + ((exp2f(b.x - m) + exp2f(b.y - m)) + (exp2f(b.z - m) + exp2f(b.w - m)));
        }
    }

    // block (m,s) combine -> scalar c
    #pragma unroll
    for (int o = 16; o; o >>= 1) {
        float mo = __shfl_xor_sync(0xffffffffu, m, o);
        float so = __shfl_xor_sync(0xffffffffu, s, o);
        float nm = fmaxf(m, mo);
        s = s * exp2f(m - nm) + so * exp2f(mo - nm);
        m = nm;
    }
    if (lane == 0) { redm[wid] = m; reds[wid] = s; }
    __syncthreads();
    if (wid == 0) {
        float mm = redm[lane];              // NWARP == 32: every lane valid
        float ss = reds[lane];
        #pragma unroll
        for (int o = 16; o; o >>= 1) {
            float mo = __shfl_xor_sync(0xffffffffu, mm, o);
            float so = __shfl_xor_sync(0xffffffffu, ss, o);
            float nm = fmaxf(mm, mo);
            ss = ss * exp2f(mm - nm) + so * exp2f(mo - nm);
            mm = nm;
        }
        if (lane == 0) cbox = mm + log2f(ss);
    }
    __syncthreads();
    const float c  = cbox;
    const float l0 = log2m[0];
    const float y0 = ybuf[0];

    // ---- Phase 2: L2 re-read (streaming), bin, DRAM write (streaming) ----
    const float4* cp4 = reinterpret_cast<const float4*>(rowp);
    float4*       op4 = reinterpret_cast<float4*>(out + row * (long long)C);

    #pragma unroll 4
    for (int i = tid; i < C4; i += THREADS) {
        float4 v = __ldcs(cp4 + i);          // evict-first: frees L2 as consumed
        float4 r;
        float* vp = &v.x;
        float* rp = &r.x;
        #pragma unroll
        for (int j = 0; j < 4; j++) {
            const float w = fmaf(vp[j], s2, -c);
            if (w <= l0) {
                rp[j] = y0;               // warp-uniform fast path (~all of a softmax row)
            } else {
                int lo = 1, hi = NMIDS;   // log2m[0] < w already established
                while (lo < hi) {
                    int mid = (lo + hi) >> 1;
                    if (log2m[mid] < w) lo = mid + 1; else hi = mid;
                }
                rp[j] = ybuf[lo];
            }
        }
        __stcs(op4 + i, r);                  // don't pollute L2
    }
}

extern "C" void kernel_launch(void* const* d_in, const int* in_sizes, int n_in,
                              void* d_out, int out_size) {
    const float* logits   = (const float*)d_in[0];
    const float* log_temp = (const float*)d_in[1];
    const float* iso_x    = (const float*)d_in[2];
    const float* iso_y    = (const float*)d_in[3];
    float* out = (float*)d_out;

    const int rows = out_size / C;
    calib_kernel<<<rows, THREADS>>>(logits, log_temp, iso_x, iso_y, out);
}